// round 8
// baseline (speedup 1.0000x reference)
#include <cuda_runtime.h>
#include <cuda_bf16.h>
#include <math_constants.h>

// Problem shape (fixed by the dataset):
//   z_latents:  [128,32,32,64] f32  -> N = 131072 rows, D = 64
//   embeddings: [64,1024]      f32  -> D = 64, K = 1024
// Output: quantized_st (8388608 f32) then vq_loss (1 f32).

#define N_ROWS   131072
#define DIM      64
#define KCODES   1024
#define KCHUNK   128
#define THREADS  128
#define ROWS_CTA 512                       // 4 rows per thread
#define NBLOCKS  (N_ROWS / ROWS_CTA)       // 256
#define ZSTRIDE  516                       // words per d-plane (512 + 4 pad, 16B-aligned)

// Scratch (no allocations allowed):
__device__ float  g_cbT[KCODES * DIM];     // codebook transposed [K][D] for row gather
__device__ float  g_se[KCODES];            // sum_d e[d][k]^2 (square-then-add, ascending d)
__device__ double g_partials[NBLOCKS];     // per-CTA loss partial sums

// ---------------- packed f32x2 helpers ----------------
__device__ __forceinline__ unsigned long long ffma2(unsigned long long a,
                                                    unsigned long long b,
                                                    unsigned long long c) {
    unsigned long long d;
    asm("fma.rn.f32x2 %0, %1, %2, %3;" : "=l"(d) : "l"(a), "l"(b), "l"(c));
    return d;
}
// swap the two fp32 lanes of a u64 (register-pair reversal)
__device__ __forceinline__ unsigned long long swp(unsigned long long v) {
    unsigned long long r;
    asm("{\n\t.reg .b32 lo, hi;\n\tmov.b64 {lo,hi}, %1;\n\tmov.b64 %0, {hi,lo};\n\t}"
        : "=l"(r) : "l"(v));
    return r;
}
__device__ __forceinline__ float2 u2f2(unsigned long long v) {
    float2 f;
    asm("mov.b64 {%0, %1}, %2;" : "=f"(f.x), "=f"(f.y) : "l"(v));
    return f;
}

// ---------------- prep: transpose codebook + per-code squared norms ----------------
__global__ void vq_prep(const float* __restrict__ emb) {
    int k = blockIdx.x * blockDim.x + threadIdx.x;
    if (k < KCODES) {
        float s = 0.0f;
        #pragma unroll
        for (int d = 0; d < DIM; ++d) {
            float v = emb[d * KCODES + k];        // coalesced across k
            g_cbT[k * DIM + d] = v;
            s = __fadd_rn(s, __fmul_rn(v, v));    // square then add, ascending d
        }
        g_se[k] = s;
    }
}

// ---------------- main ----------------
// dynamic smem layout (floats):
//   zT  : [64][ZSTRIDE]  transposed z, rows of this CTA          33024 f
//   cbs : [64][KCHUNK]   codebook chunk, k-within-chunk major     8192 f
//   ses : [KCHUNK]                                                 128 f
//   szs : [ROWS_CTA]     per-row sum z^2                           512 f
//   wsm : 4 doubles                                                  8 f
#define ZT_OFF   0
#define CBS_OFF  (64 * ZSTRIDE)
#define SES_OFF  (CBS_OFF + 64 * KCHUNK)
#define SZS_OFF  (SES_OFF + KCHUNK)
#define WSM_OFF  (SZS_OFF + ROWS_CTA)
#define SMEM_BYTES ((WSM_OFF + 8) * 4)

__global__ void __launch_bounds__(THREADS, 1)
vq_main(const float* __restrict__ z,
        const float* __restrict__ emb,
        float* __restrict__ out)
{
    extern __shared__ float smem[];
    float*  zT  = smem + ZT_OFF;
    float*  cbs = smem + CBS_OFF;
    float*  ses = smem + SES_OFF;
    float*  szs = smem + SZS_OFF;
    double* wsm = (double*)(smem + WSM_OFF);

    const int b = blockIdx.x;
    const int t = threadIdx.x;

    // ---- stage: transpose this CTA's 512 z rows into zT[d][row]; per-row sz ----
    const float* zg = z + (size_t)b * ROWS_CTA * DIM;
    #pragma unroll
    for (int rr = 0; rr < 4; ++rr) {
        int r = t + rr * THREADS;                          // row within CTA
        const float4* zr4 = (const float4*)(zg + (size_t)r * DIM);
        float s = 0.0f;
        #pragma unroll
        for (int j = 0; j < 16; ++j) {
            float4 v = zr4[j];
            zT[(4 * j + 0) * ZSTRIDE + r] = v.x;           // conflict-free: bank = (r + c)%32
            zT[(4 * j + 1) * ZSTRIDE + r] = v.y;
            zT[(4 * j + 2) * ZSTRIDE + r] = v.z;
            zT[(4 * j + 3) * ZSTRIDE + r] = v.w;
            s = __fadd_rn(s, __fmul_rn(v.x, v.x));         // sequential ascending d
            s = __fadd_rn(s, __fmul_rn(v.y, v.y));
            s = __fadd_rn(s, __fmul_rn(v.z, v.z));
            s = __fadd_rn(s, __fmul_rn(v.w, v.w));
        }
        szs[r] = s;
    }
    __syncthreads();

    // this thread owns rows 4t .. 4t+3
    float sz[4];
    #pragma unroll
    for (int rr = 0; rr < 4; ++rr) sz[rr] = szs[4 * t + rr];

    float best[4] = {CUDART_INF_F, CUDART_INF_F, CUDART_INF_F, CUDART_INF_F};
    int   bi[4]   = {0, 0, 0, 0};

    const ulonglong2* zzp = (const ulonglong2*)(zT) ;      // indexed per-d below

    for (int k0 = 0; k0 < KCODES; k0 += KCHUNK) {
        __syncthreads();
        // load codebook chunk: cbs[d][kc], coalesced 512B rows
        #pragma unroll 4
        for (int i = t; i < DIM * KCHUNK; i += THREADS)
            cbs[i] = emb[(i >> 7) * KCODES + k0 + (i & (KCHUNK - 1))];
        ses[t] = g_se[k0 + t];
        __syncthreads();

        const ulonglong2* cb2base = (const ulonglong2*)cbs;   // 32 per d-row

        for (int kg = 0; kg < KCHUNK; kg += 8) {
            const ulonglong2* cb2 = cb2base + (kg >> 2);
            // accF/accR: [row-pair][code-pair]; fwd and swapped-e accumulators
            unsigned long long aF0[4] = {0,0,0,0}, aR0[4] = {0,0,0,0};
            unsigned long long aF1[4] = {0,0,0,0}, aR1[4] = {0,0,0,0};
            #pragma unroll
            for (int d = 0; d < DIM; ++d) {
                ulonglong2 zz = zzp[(d * ZSTRIDE) / 4 + t];   // (z0,z1),(z2,z3) rows 4t..4t+3
                ulonglong2 e0 = cb2[d * (KCHUNK / 4)];        // code pairs (kg,kg+1),(kg+2,kg+3)
                ulonglong2 e1 = cb2[d * (KCHUNK / 4) + 1];    // (kg+4,kg+5),(kg+6,kg+7)
                unsigned long long s0 = swp(e0.x), s1 = swp(e0.y);
                unsigned long long s2 = swp(e1.x), s3 = swp(e1.y);
                aF0[0] = ffma2(zz.x, e0.x, aF0[0]);  aR0[0] = ffma2(zz.x, s0, aR0[0]);
                aF0[1] = ffma2(zz.x, e0.y, aF0[1]);  aR0[1] = ffma2(zz.x, s1, aR0[1]);
                aF0[2] = ffma2(zz.x, e1.x, aF0[2]);  aR0[2] = ffma2(zz.x, s2, aR0[2]);
                aF0[3] = ffma2(zz.x, e1.y, aF0[3]);  aR0[3] = ffma2(zz.x, s3, aR0[3]);
                aF1[0] = ffma2(zz.y, e0.x, aF1[0]);  aR1[0] = ffma2(zz.y, s0, aR1[0]);
                aF1[1] = ffma2(zz.y, e0.y, aF1[1]);  aR1[1] = ffma2(zz.y, s1, aR1[1]);
                aF1[2] = ffma2(zz.y, e1.x, aF1[2]);  aR1[2] = ffma2(zz.y, s2, aR1[2]);
                aF1[3] = ffma2(zz.y, e1.y, aF1[3]);  aR1[3] = ffma2(zz.y, s3, aR1[3]);
            }
            // unpack: per code pair q, lanes give the 4 cross dot-products
            float2 f0[4], r0[4], f1[4], r1[4];
            #pragma unroll
            for (int q = 0; q < 4; ++q) {
                f0[q] = u2f2(aF0[q]);  r0[q] = u2f2(aR0[q]);
                f1[q] = u2f2(aF1[q]);  r1[q] = u2f2(aR1[q]);
            }
            // ascending code order, strict < (first-occurrence tie-break)
            #pragma unroll
            for (int j = 0; j < 8; ++j) {
                int   q   = j >> 1;
                bool  odd = j & 1;
                float se  = ses[kg + j];
                int   kk  = k0 + kg + j;
                // dot(row, code kk): fwd lane-lo = even row/even code, etc.
                float d0 = odd ? r0[q].x : f0[q].x;   // row 4t+0
                float d1 = odd ? f0[q].y : r0[q].y;   // row 4t+1
                float d2 = odd ? r1[q].x : f1[q].x;   // row 4t+2
                float d3 = odd ? f1[q].y : r1[q].y;   // row 4t+3
                float q0 = __fadd_rn(__fsub_rn(sz[0], __fmul_rn(2.0f, d0)), se);
                float q1 = __fadd_rn(__fsub_rn(sz[1], __fmul_rn(2.0f, d1)), se);
                float q2 = __fadd_rn(__fsub_rn(sz[2], __fmul_rn(2.0f, d2)), se);
                float q3 = __fadd_rn(__fsub_rn(sz[3], __fmul_rn(2.0f, d3)), se);
                if (q0 < best[0]) { best[0] = q0; bi[0] = kk; }
                if (q1 < best[1]) { best[1] = q1; bi[1] = kk; }
                if (q2 < best[2]) { best[2] = q2; bi[2] = kk; }
                if (q3 < best[3]) { best[3] = q3; bi[3] = kk; }
            }
        }
    }

    // ---- gather chosen rows, straight-through output, loss partial ----
    double lsum = 0.0;
    #pragma unroll
    for (int rr = 0; rr < 4; ++rr) {
        int r = 4 * t + rr;
        const float4* qrow = (const float4*)(g_cbT + (size_t)bi[rr] * DIM);
        float4* orow = (float4*)(out + ((size_t)b * ROWS_CTA + r) * DIM);
        #pragma unroll
        for (int j = 0; j < DIM / 4; ++j) {
            float4 q4 = qrow[j];
            float z0 = zT[(4 * j + 0) * ZSTRIDE + r];
            float z1 = zT[(4 * j + 1) * ZSTRIDE + r];
            float z2 = zT[(4 * j + 2) * ZSTRIDE + r];
            float z3 = zT[(4 * j + 3) * ZSTRIDE + r];
            float4 o4;
            float d0 = __fsub_rn(q4.x, z0);  o4.x = __fadd_rn(z0, d0);
            float d1 = __fsub_rn(q4.y, z1);  o4.y = __fadd_rn(z1, d1);
            float d2 = __fsub_rn(q4.z, z2);  o4.z = __fadd_rn(z2, d2);
            float d3 = __fsub_rn(q4.w, z3);  o4.w = __fadd_rn(z3, d3);
            lsum += (double)__fmul_rn(d0, d0) + (double)__fmul_rn(d1, d1)
                  + (double)__fmul_rn(d2, d2) + (double)__fmul_rn(d3, d3);
            orow[j] = o4;
        }
    }

    // deterministic block reduction (4 warps)
    #pragma unroll
    for (int o = 16; o > 0; o >>= 1)
        lsum += __shfl_down_sync(0xffffffffu, lsum, o);
    if ((t & 31) == 0) wsm[t >> 5] = lsum;
    __syncthreads();
    if (t == 0) {
        double s = 0.0;
        #pragma unroll
        for (int w = 0; w < THREADS / 32; ++w) s += wsm[w];
        g_partials[b] = s;
    }
}

// ---------------- finish: reduce partials, emit vq_loss ----------------
__global__ void vq_finish(float* __restrict__ out) {
    __shared__ double sm[256];
    int t = threadIdx.x;
    sm[t] = g_partials[t];                 // NBLOCKS == 256
    __syncthreads();
    #pragma unroll
    for (int s = 128; s > 0; s >>= 1) {
        if (t < s) sm[t] += sm[t + s];
        __syncthreads();
    }
    if (t == 0) {
        float L = (float)(sm[0] / (double)(N_ROWS * DIM));
        out[N_ROWS * DIM] = __fadd_rn(L, __fmul_rn(0.25f, L));
    }
}

extern "C" void kernel_launch(void* const* d_in, const int* in_sizes, int n_in,
                              void* d_out, int out_size) {
    const float* z   = (const float*)d_in[0];
    const float* emb = (const float*)d_in[1];
    float* out = (float*)d_out;

    (void)in_sizes; (void)n_in; (void)out_size;

    cudaFuncSetAttribute(vq_main, cudaFuncAttributeMaxDynamicSharedMemorySize, SMEM_BYTES);

    vq_prep<<<(KCODES + 255) / 256, 256>>>(emb);
    vq_main<<<NBLOCKS, THREADS, SMEM_BYTES>>>(z, emb, out);
    vq_finish<<<1, 256>>>(out);
}

// round 9
// speedup vs baseline: 1.0003x; 1.0003x over previous
#include <cuda_runtime.h>
#include <cuda_bf16.h>
#include <math_constants.h>

// Problem shape (fixed by the dataset):
//   z_latents:  [128,32,32,64] f32  -> N = 131072 rows, D = 64
//   embeddings: [64,1024]      f32  -> D = 64, K = 1024
// Output: quantized_st (8388608 f32) then vq_loss (1 f32).

#define N_ROWS   131072
#define DIM      64
#define KCODES   1024
#define KCHUNK   128
#define THREADS  128
#define ROWS_CTA 512                       // 4 rows per thread
#define NBLOCKS  (N_ROWS / ROWS_CTA)       // 256
#define ZSTRIDE  516                       // words per d-plane (512 + 4 pad, 16B-aligned)

// Scratch (no allocations allowed):
__device__ float  g_cbT[KCODES * DIM];     // codebook transposed [K][D] for row gather
__device__ float  g_se[KCODES];            // sum_d e[d][k]^2 (square-then-add, ascending d)
__device__ double g_partials[NBLOCKS];     // per-CTA loss partial sums

// ---------------- packed f32x2 helpers ----------------
__device__ __forceinline__ unsigned long long ffma2(unsigned long long a,
                                                    unsigned long long b,
                                                    unsigned long long c) {
    unsigned long long d;
    asm("fma.rn.f32x2 %0, %1, %2, %3;" : "=l"(d) : "l"(a), "l"(b), "l"(c));
    return d;
}
// swap the two fp32 lanes of a u64 (register-pair reversal)
__device__ __forceinline__ unsigned long long swp(unsigned long long v) {
    unsigned long long r;
    asm("{\n\t.reg .b32 lo, hi;\n\tmov.b64 {lo,hi}, %1;\n\tmov.b64 %0, {hi,lo};\n\t}"
        : "=l"(r) : "l"(v));
    return r;
}
__device__ __forceinline__ float2 u2f2(unsigned long long v) {
    float2 f;
    asm("mov.b64 {%0, %1}, %2;" : "=f"(f.x), "=f"(f.y) : "l"(v));
    return f;
}

// ---------------- prep: transpose codebook + per-code squared norms ----------------
__global__ void vq_prep(const float* __restrict__ emb) {
    int k = blockIdx.x * blockDim.x + threadIdx.x;
    if (k < KCODES) {
        float s = 0.0f;
        #pragma unroll
        for (int d = 0; d < DIM; ++d) {
            float v = emb[d * KCODES + k];        // coalesced across k
            g_cbT[k * DIM + d] = v;
            s = __fadd_rn(s, __fmul_rn(v, v));    // square then add, ascending d
        }
        g_se[k] = s;
    }
}

// ---------------- main ----------------
// dynamic smem layout (floats):
//   zT  : [64][ZSTRIDE]  transposed z, rows of this CTA          33024 f
//   cbs : [64][KCHUNK]   codebook chunk, k-within-chunk major     8192 f
//   ses : [KCHUNK]                                                 128 f
//   szs : [ROWS_CTA]     per-row sum z^2                           512 f
//   wsm : 4 doubles                                                  8 f
#define ZT_OFF   0
#define CBS_OFF  (64 * ZSTRIDE)
#define SES_OFF  (CBS_OFF + 64 * KCHUNK)
#define SZS_OFF  (SES_OFF + KCHUNK)
#define WSM_OFF  (SZS_OFF + ROWS_CTA)
#define SMEM_BYTES ((WSM_OFF + 8) * 4)

__global__ void __launch_bounds__(THREADS, 1)
vq_main(const float* __restrict__ z,
        const float* __restrict__ emb,
        float* __restrict__ out)
{
    extern __shared__ float smem[];
    float*  zT  = smem + ZT_OFF;
    float*  cbs = smem + CBS_OFF;
    float*  ses = smem + SES_OFF;
    float*  szs = smem + SZS_OFF;
    double* wsm = (double*)(smem + WSM_OFF);

    const int b = blockIdx.x;
    const int t = threadIdx.x;

    // ---- stage: transpose this CTA's 512 z rows into zT[d][row]; per-row sz ----
    const float* zg = z + (size_t)b * ROWS_CTA * DIM;
    #pragma unroll
    for (int rr = 0; rr < 4; ++rr) {
        int r = t + rr * THREADS;                          // row within CTA
        const float4* zr4 = (const float4*)(zg + (size_t)r * DIM);
        float s = 0.0f;
        #pragma unroll
        for (int j = 0; j < 16; ++j) {
            float4 v = zr4[j];
            zT[(4 * j + 0) * ZSTRIDE + r] = v.x;           // conflict-free: bank = (r + c)%32
            zT[(4 * j + 1) * ZSTRIDE + r] = v.y;
            zT[(4 * j + 2) * ZSTRIDE + r] = v.z;
            zT[(4 * j + 3) * ZSTRIDE + r] = v.w;
            s = __fadd_rn(s, __fmul_rn(v.x, v.x));         // sequential ascending d
            s = __fadd_rn(s, __fmul_rn(v.y, v.y));
            s = __fadd_rn(s, __fmul_rn(v.z, v.z));
            s = __fadd_rn(s, __fmul_rn(v.w, v.w));
        }
        szs[r] = s;
    }
    __syncthreads();

    // this thread owns rows 4t .. 4t+3
    float sz[4];
    #pragma unroll
    for (int rr = 0; rr < 4; ++rr) sz[rr] = szs[4 * t + rr];

    float best[4] = {CUDART_INF_F, CUDART_INF_F, CUDART_INF_F, CUDART_INF_F};
    int   bi[4]   = {0, 0, 0, 0};

    const ulonglong2* zzp = (const ulonglong2*)(zT) ;      // indexed per-d below

    for (int k0 = 0; k0 < KCODES; k0 += KCHUNK) {
        __syncthreads();
        // load codebook chunk: cbs[d][kc], coalesced 512B rows
        #pragma unroll 4
        for (int i = t; i < DIM * KCHUNK; i += THREADS)
            cbs[i] = emb[(i >> 7) * KCODES + k0 + (i & (KCHUNK - 1))];
        ses[t] = g_se[k0 + t];
        __syncthreads();

        const ulonglong2* cb2base = (const ulonglong2*)cbs;   // 32 per d-row

        for (int kg = 0; kg < KCHUNK; kg += 8) {
            const ulonglong2* cb2 = cb2base + (kg >> 2);
            // accF/accR: [row-pair][code-pair]; fwd and swapped-e accumulators
            unsigned long long aF0[4] = {0,0,0,0}, aR0[4] = {0,0,0,0};
            unsigned long long aF1[4] = {0,0,0,0}, aR1[4] = {0,0,0,0};
            #pragma unroll
            for (int d = 0; d < DIM; ++d) {
                ulonglong2 zz = zzp[(d * ZSTRIDE) / 4 + t];   // (z0,z1),(z2,z3) rows 4t..4t+3
                ulonglong2 e0 = cb2[d * (KCHUNK / 4)];        // code pairs (kg,kg+1),(kg+2,kg+3)
                ulonglong2 e1 = cb2[d * (KCHUNK / 4) + 1];    // (kg+4,kg+5),(kg+6,kg+7)
                unsigned long long s0 = swp(e0.x), s1 = swp(e0.y);
                unsigned long long s2 = swp(e1.x), s3 = swp(e1.y);
                aF0[0] = ffma2(zz.x, e0.x, aF0[0]);  aR0[0] = ffma2(zz.x, s0, aR0[0]);
                aF0[1] = ffma2(zz.x, e0.y, aF0[1]);  aR0[1] = ffma2(zz.x, s1, aR0[1]);
                aF0[2] = ffma2(zz.x, e1.x, aF0[2]);  aR0[2] = ffma2(zz.x, s2, aR0[2]);
                aF0[3] = ffma2(zz.x, e1.y, aF0[3]);  aR0[3] = ffma2(zz.x, s3, aR0[3]);
                aF1[0] = ffma2(zz.y, e0.x, aF1[0]);  aR1[0] = ffma2(zz.y, s0, aR1[0]);
                aF1[1] = ffma2(zz.y, e0.y, aF1[1]);  aR1[1] = ffma2(zz.y, s1, aR1[1]);
                aF1[2] = ffma2(zz.y, e1.x, aF1[2]);  aR1[2] = ffma2(zz.y, s2, aR1[2]);
                aF1[3] = ffma2(zz.y, e1.y, aF1[3]);  aR1[3] = ffma2(zz.y, s3, aR1[3]);
            }
            // unpack: per code pair q, lanes give the 4 cross dot-products
            float2 f0[4], r0[4], f1[4], r1[4];
            #pragma unroll
            for (int q = 0; q < 4; ++q) {
                f0[q] = u2f2(aF0[q]);  r0[q] = u2f2(aR0[q]);
                f1[q] = u2f2(aF1[q]);  r1[q] = u2f2(aR1[q]);
            }
            // ascending code order, strict < (first-occurrence tie-break)
            #pragma unroll
            for (int j = 0; j < 8; ++j) {
                int   q   = j >> 1;
                bool  odd = j & 1;
                float se  = ses[kg + j];
                int   kk  = k0 + kg + j;
                // dot(row, code kk): fwd lane-lo = even row/even code, etc.
                float d0 = odd ? r0[q].x : f0[q].x;   // row 4t+0
                float d1 = odd ? f0[q].y : r0[q].y;   // row 4t+1
                float d2 = odd ? r1[q].x : f1[q].x;   // row 4t+2
                float d3 = odd ? f1[q].y : r1[q].y;   // row 4t+3
                float q0 = __fadd_rn(__fsub_rn(sz[0], __fmul_rn(2.0f, d0)), se);
                float q1 = __fadd_rn(__fsub_rn(sz[1], __fmul_rn(2.0f, d1)), se);
                float q2 = __fadd_rn(__fsub_rn(sz[2], __fmul_rn(2.0f, d2)), se);
                float q3 = __fadd_rn(__fsub_rn(sz[3], __fmul_rn(2.0f, d3)), se);
                if (q0 < best[0]) { best[0] = q0; bi[0] = kk; }
                if (q1 < best[1]) { best[1] = q1; bi[1] = kk; }
                if (q2 < best[2]) { best[2] = q2; bi[2] = kk; }
                if (q3 < best[3]) { best[3] = q3; bi[3] = kk; }
            }
        }
    }

    // ---- gather chosen rows, straight-through output, loss partial ----
    double lsum = 0.0;
    #pragma unroll
    for (int rr = 0; rr < 4; ++rr) {
        int r = 4 * t + rr;
        const float4* qrow = (const float4*)(g_cbT + (size_t)bi[rr] * DIM);
        float4* orow = (float4*)(out + ((size_t)b * ROWS_CTA + r) * DIM);
        #pragma unroll
        for (int j = 0; j < DIM / 4; ++j) {
            float4 q4 = qrow[j];
            float z0 = zT[(4 * j + 0) * ZSTRIDE + r];
            float z1 = zT[(4 * j + 1) * ZSTRIDE + r];
            float z2 = zT[(4 * j + 2) * ZSTRIDE + r];
            float z3 = zT[(4 * j + 3) * ZSTRIDE + r];
            float4 o4;
            float d0 = __fsub_rn(q4.x, z0);  o4.x = __fadd_rn(z0, d0);
            float d1 = __fsub_rn(q4.y, z1);  o4.y = __fadd_rn(z1, d1);
            float d2 = __fsub_rn(q4.z, z2);  o4.z = __fadd_rn(z2, d2);
            float d3 = __fsub_rn(q4.w, z3);  o4.w = __fadd_rn(z3, d3);
            lsum += (double)__fmul_rn(d0, d0) + (double)__fmul_rn(d1, d1)
                  + (double)__fmul_rn(d2, d2) + (double)__fmul_rn(d3, d3);
            orow[j] = o4;
        }
    }

    // deterministic block reduction (4 warps)
    #pragma unroll
    for (int o = 16; o > 0; o >>= 1)
        lsum += __shfl_down_sync(0xffffffffu, lsum, o);
    if ((t & 31) == 0) wsm[t >> 5] = lsum;
    __syncthreads();
    if (t == 0) {
        double s = 0.0;
        #pragma unroll
        for (int w = 0; w < THREADS / 32; ++w) s += wsm[w];
        g_partials[b] = s;
    }
}

// ---------------- finish: reduce partials, emit vq_loss ----------------
__global__ void vq_finish(float* __restrict__ out) {
    __shared__ double sm[256];
    int t = threadIdx.x;
    sm[t] = g_partials[t];                 // NBLOCKS == 256
    __syncthreads();
    #pragma unroll
    for (int s = 128; s > 0; s >>= 1) {
        if (t < s) sm[t] += sm[t + s];
        __syncthreads();
    }
    if (t == 0) {
        float L = (float)(sm[0] / (double)(N_ROWS * DIM));
        out[N_ROWS * DIM] = __fadd_rn(L, __fmul_rn(0.25f, L));
    }
}

extern "C" void kernel_launch(void* const* d_in, const int* in_sizes, int n_in,
                              void* d_out, int out_size) {
    const float* z   = (const float*)d_in[0];
    const float* emb = (const float*)d_in[1];
    float* out = (float*)d_out;

    (void)in_sizes; (void)n_in; (void)out_size;

    cudaFuncSetAttribute(vq_main, cudaFuncAttributeMaxDynamicSharedMemorySize, SMEM_BYTES);

    vq_prep<<<(KCODES + 255) / 256, 256>>>(emb);
    vq_main<<<NBLOCKS, THREADS, SMEM_BYTES>>>(z, emb, out);
    vq_finish<<<1, 256>>>(out);
}